// round 10
// baseline (speedup 1.0000x reference)
#include <cuda_runtime.h>
#include <math.h>
#include <float.h>

// Problem constants: B=4, C=1024, DK=1024, 3DK=3072, size = out_size/(B*DK)
#define BB 4
#define CC 1024
#define DK 1024
#define DK4 (DK / 4)          // 256 float4 per row
#define TDK 3072
#define TDK4 (TDK / 4)        // 768 float4 per W row
#define NSEG 64
#define CSEG (CC / NSEG)      // 16
#define CHUNK 32
#define MAXCH 128             // supports size up to 4096 (this problem: 4096)

// -------- scratch (device globals) --------
__device__ float4   g_qkv_part[NSEG * BB * TDK4];   // projection partials (float4)
__device__ float    g_qkv[BB * TDK];                // q | k_new | v_new
__device__ float    g_se[BB * MAXCH];               // per-chunk scalar e-sums
// TRANSPOSED: [b][c4][ch] so the prefix scan reads contiguous runs per column
__device__ float4   g_P[BB * DK4 * MAXCH];
__device__ unsigned g_bar[2];                       // grid barrier counters

// ---------------- K1: QKV projection partials (float4 W loads) --------------
// grid (TDK4/256 = 3, NSEG = 64), block 256. Thread owns one float4 of j.
__global__ void __launch_bounds__(256)
k_proj_partial(const float* __restrict__ x, const float4* __restrict__ W4, int S) {
    int j4  = blockIdx.x * 256 + threadIdx.x;   // 0..767
    int seg = blockIdx.y;
    int c0  = seg * CSEG;

    __shared__ float xs[BB][CSEG];
    if (threadIdx.x < BB * CSEG) {
        int b = threadIdx.x / CSEG, cc = threadIdx.x % CSEG;
        xs[b][cc] = x[(size_t)b * S * CC + (size_t)(S - 1) * CC + c0 + cc];
    }
    __syncthreads();

    float4 a0 = make_float4(0.f, 0.f, 0.f, 0.f);
    float4 a1 = a0, a2 = a0, a3 = a0;
#pragma unroll
    for (int cc = 0; cc < CSEG; cc++) {
        float4 w = __ldcs(&W4[(size_t)(c0 + cc) * TDK4 + j4]);
        float x0 = xs[0][cc], x1 = xs[1][cc], x2 = xs[2][cc], x3 = xs[3][cc];
        a0.x += x0 * w.x; a0.y += x0 * w.y; a0.z += x0 * w.z; a0.w += x0 * w.w;
        a1.x += x1 * w.x; a1.y += x1 * w.y; a1.z += x1 * w.z; a1.w += x1 * w.w;
        a2.x += x2 * w.x; a2.y += x2 * w.y; a2.z += x2 * w.z; a2.w += x2 * w.w;
        a3.x += x3 * w.x; a3.y += x3 * w.y; a3.z += x3 * w.z; a3.w += x3 * w.w;
    }
    g_qkv_part[(size_t)(seg * BB + 0) * TDK4 + j4] = a0;
    g_qkv_part[(size_t)(seg * BB + 1) * TDK4 + j4] = a1;
    g_qkv_part[(size_t)(seg * BB + 2) * TDK4 + j4] = a2;
    g_qkv_part[(size_t)(seg * BB + 3) * TDK4 + j4] = a3;
}

// ---------------- K1b: reduce partials + bias (float4); reset barriers ------
// grid 12, block 256 -> BB*TDK4 = 3072 threads
__global__ void __launch_bounds__(256)
k_init_reduce(const float4* __restrict__ bias4) {
    int idx = blockIdx.x * 256 + threadIdx.x;
    if (idx < 2) g_bar[idx] = 0u;
    if (idx >= BB * TDK4) return;
    int b = idx / TDK4, j4 = idx % TDK4;
    float4 s = bias4[j4];
#pragma unroll 8
    for (int seg = 0; seg < NSEG; seg++) {
        float4 p = g_qkv_part[(size_t)(seg * BB + b) * TDK4 + j4];
        s.x += p.x; s.y += p.y; s.z += p.z; s.w += p.w;
    }
    ((float4*)g_qkv)[(size_t)b * TDK4 + j4] = s;
}

// ---------------- software grid barrier (all blocks co-resident) ------------
__device__ __forceinline__ void grid_barrier(unsigned* bar, unsigned expected) {
    __syncthreads();
    if (threadIdx.x == 0) {
        __threadfence();                         // publish this block's writes
        atomicAdd(bar, 1u);
        volatile unsigned* vb = bar;
        while (*vb < expected) { }
    }
    __syncthreads();
}

// ---------------- K2: MEGA — logits+exp+partials | prefix | output ----------
// grid (nch, B), block 256 (8 warps). Must be fully co-resident (512 blocks).
__global__ void __launch_bounds__(256)
k_mega(const float* __restrict__ kc, const float4* __restrict__ vc4,
       float4* __restrict__ out4, int ML, int size, int tok, int nch) {
    int b    = blockIdx.y;
    int ch   = blockIdx.x;
    int tid  = threadIdx.x;
    int warp = tid >> 5;
    int lane = tid & 31;
    int t0   = ch * CHUNK;
    int t1   = min(t0 + CHUNK, size);
    unsigned expected = gridDim.x * gridDim.y;

    __shared__ float qs[DK];
    __shared__ float es[CHUNK];      // exp values (live across phases)
    __shared__ float run[CHUNK];     // inclusive scalar prefix within chunk
    __shared__ float ssum[MAXCH];
    __shared__ float sbase[1];

    // ================= Phase 1: logits + exp + chunk partials ==============
    for (int i = tid; i < DK; i += 256)
        qs[i] = g_qkv[(size_t)b * TDK + i];
    __syncthreads();

#pragma unroll
    for (int r = 0; r < 4; r++) {
        int t = t0 + warp * 4 + r;
        float acc = 0.f;
        if (t < size) {
            const float* krow = (t == tok) ? (g_qkv + (size_t)b * TDK + DK)
                                           : (kc + ((size_t)b * ML + t) * DK);
#pragma unroll
            for (int i = 0; i < 8; i++) {
                float4 kv = __ldcs((const float4*)(krow + i * 128 + lane * 4));
                float4 qv = *(const float4*)(qs + i * 128 + lane * 4);
                acc += kv.x * qv.x + kv.y * qv.y + kv.z * qv.z + kv.w * qv.w;
            }
#pragma unroll
            for (int o = 16; o; o >>= 1) acc += __shfl_xor_sync(0xFFFFFFFFu, acc, o);
        }
        if (lane == 0)
            es[warp * 4 + r] = (t < size) ? __expf(acc * 0.03125f) : 0.f;
    }
    __syncthreads();

    // intra-chunk scalar scan + chunk sum (warp 0)
    if (tid < 32) {
        float e = es[tid];
        float v = e;
#pragma unroll
        for (int o = 1; o < 32; o <<= 1) {
            float u = __shfl_up_sync(0xFFFFFFFFu, v, o);
            if (tid >= o) v += u;
        }
        run[tid] = v;
        float s = __shfl_sync(0xFFFFFFFFu, v, 31);
        if (tid == 0) g_se[(size_t)b * MAXCH + ch] = s;
    }
    __syncthreads();

    // vector partial over this chunk (V lands in this SM's L1 + L2)
    const float4* vb = vc4 + (size_t)b * ML * DK4;
    float4 vnew = *(const float4*)(g_qkv + (size_t)b * TDK + 2 * DK + 4 * tid);
    {
        float4 acc = make_float4(0.f, 0.f, 0.f, 0.f);
#pragma unroll 4
        for (int t = t0; t < t1; t++) {
            float4 v = (t == tok) ? vnew : __ldg(&vb[(size_t)t * DK4 + tid]);
            float e = es[t - t0];
            acc.x += e * v.x; acc.y += e * v.y; acc.z += e * v.z; acc.w += e * v.w;
        }
        g_P[((size_t)b * DK4 + tid) * MAXCH + ch] = acc;
    }

    grid_barrier(&g_bar[0], expected);

    // ================= Phase 2: warp-per-column exclusive prefix ============
    {
        int gbid = blockIdx.y * gridDim.x + blockIdx.x;
        int gw   = gbid * 8 + warp;             // global warp id
        if (gw < BB * DK4) {
            float4* col = g_P + (size_t)gw * MAXCH;
            int base = lane * 4;
            float4 z = make_float4(0.f, 0.f, 0.f, 0.f);
            float4 v0 = (base + 0 < nch) ? __ldcg(&col[base + 0]) : z;
            float4 v1 = (base + 1 < nch) ? __ldcg(&col[base + 1]) : z;
            float4 v2 = (base + 2 < nch) ? __ldcg(&col[base + 2]) : z;
            float4 v3 = (base + 3 < nch) ? __ldcg(&col[base + 3]) : z;

            float4 tot = make_float4(v0.x + v1.x + v2.x + v3.x,
                                     v0.y + v1.y + v2.y + v3.y,
                                     v0.z + v1.z + v2.z + v3.z,
                                     v0.w + v1.w + v2.w + v3.w);
            float4 sc = tot;
#pragma unroll
            for (int o = 1; o < 32; o <<= 1) {
                float ux = __shfl_up_sync(0xFFFFFFFFu, sc.x, o);
                float uy = __shfl_up_sync(0xFFFFFFFFu, sc.y, o);
                float uz = __shfl_up_sync(0xFFFFFFFFu, sc.z, o);
                float uw = __shfl_up_sync(0xFFFFFFFFu, sc.w, o);
                if (lane >= o) { sc.x += ux; sc.y += uy; sc.z += uz; sc.w += uw; }
            }
            float4 r0 = make_float4(sc.x - tot.x, sc.y - tot.y,
                                    sc.z - tot.z, sc.w - tot.w);
            float4 r1 = make_float4(r0.x + v0.x, r0.y + v0.y, r0.z + v0.z, r0.w + v0.w);
            float4 r2 = make_float4(r1.x + v1.x, r1.y + v1.y, r1.z + v1.z, r1.w + v1.w);
            float4 r3 = make_float4(r2.x + v2.x, r2.y + v2.y, r2.z + v2.z, r2.w + v2.w);
            if (base + 0 < nch) col[base + 0] = r0;
            if (base + 1 < nch) col[base + 1] = r1;
            if (base + 2 < nch) col[base + 2] = r2;
            if (base + 3 < nch) col[base + 3] = r3;
        }
    }

    grid_barrier(&g_bar[1], expected);

    // ================= Phase 3: output (same chunk -> V is L1/L2 hot) ======
    for (int i = tid; i < nch; i += 256)
        ssum[i] = __ldcg(&g_se[(size_t)b * MAXCH + i]);
    __syncthreads();
    if (tid < 32) {
        float s = 0.f;
        for (int j = tid; j < ch; j += 32) s += ssum[j];
#pragma unroll
        for (int o = 16; o; o >>= 1) s += __shfl_xor_sync(0xFFFFFFFFu, s, o);
        if (tid == 0) sbase[0] = s;
    }
    float4 acc = __ldcg(&g_P[((size_t)b * DK4 + tid) * MAXCH + ch]);
    __syncthreads();
    float base_se = sbase[0];

#pragma unroll 4
    for (int t = t0; t < t1; t++) {
        float4 v = (t == tok) ? vnew : __ldg(&vb[(size_t)t * DK4 + tid]);
        float e = es[t - t0];
        acc.x += e * v.x; acc.y += e * v.y; acc.z += e * v.z; acc.w += e * v.w;
        float d = 1.0f / (base_se + run[t - t0]);
        float4 o = make_float4(acc.x * d, acc.y * d, acc.z * d, acc.w * d);
        __stcs(&out4[((size_t)b * size + t) * DK4 + tid], o);
    }
}

// ---------------- launch ----------------
extern "C" void kernel_launch(void* const* d_in, const int* in_sizes, int n_in,
                              void* d_out, int out_size) {
    const float* x    = (const float*)d_in[0];
    const float* W    = (const float*)d_in[1];
    const float* bias = (const float*)d_in[2];
    const float* kc   = (const float*)d_in[3];
    const float* vc   = (const float*)d_in[4];
    int S    = in_sizes[0] / (BB * CC);
    int ML   = in_sizes[3] / (BB * DK);
    int size = out_size / (BB * DK);
    int tok  = size - 1;
    int nch  = (size + CHUNK - 1) / CHUNK;

    k_proj_partial<<<dim3(TDK4 / 256, NSEG), 256>>>(x, (const float4*)W, S);
    k_init_reduce<<<(BB * TDK4 + 255) / 256, 256>>>((const float4*)bias);
    k_mega<<<dim3(nch, BB), 256>>>(kc, (const float4*)vc, (float4*)d_out,
                                   ML, size, tok, nch);
}

// round 11
// speedup vs baseline: 1.0545x; 1.0545x over previous
#include <cuda_runtime.h>
#include <math.h>
#include <float.h>

// Problem constants: B=4, C=1024, DK=1024, 3DK=3072, size = out_size/(B*DK)
#define BB 4
#define CC 1024
#define DK 1024
#define DK4 (DK / 4)          // 256 float4 per row
#define TDK 3072
#define TDK4 (TDK / 4)        // 768 float4 per W row
#define NSEG 128
#define CSEG (CC / NSEG)      // 8
#define JTW 192               // j4 per tile; 4 tiles * 192 = 768
#define CHUNK 32
#define MAXCH 128             // supports size up to 4096 (this problem: 4096)

// -------- scratch (device globals; zero-initialized at module load) --------
__device__ float4   g_qkv_part[NSEG * BB * TDK4];   // projection partials
__device__ float    g_qkv[BB * TDK];                // q | k_new | v_new
__device__ float    g_se[BB * MAXCH];               // per-chunk scalar e-sums
// TRANSPOSED: [b][c4][ch] so the prefix scan reads contiguous runs per column
__device__ float4   g_P[BB * DK4 * MAXCH];
__device__ unsigned g_bar[5];                       // 4 barriers + ack counter

// ---------------- software grid barrier (all blocks co-resident) ------------
__device__ __forceinline__ void grid_barrier(unsigned* bar, unsigned expected) {
    __syncthreads();
    if (threadIdx.x == 0) {
        __threadfence();                         // publish this block's writes
        atomicAdd(bar, 1u);
        volatile unsigned* vb = bar;
        while (*vb < expected) { }
    }
    __syncthreads();
}

// ---------------- MEGA: proj | reduce | logits+partials | prefix | output ---
// grid (nch, B) = 512 blocks, 256 thr. __launch_bounds__(256,4) keeps regs<=64
// so >=4 blocks/SM -> all 512 co-resident (capacity 592) -> barriers safe.
__global__ void __launch_bounds__(256, 4)
k_mega(const float* __restrict__ x, const float4* __restrict__ W4,
       const float4* __restrict__ bias4, const float* __restrict__ kc,
       const float4* __restrict__ vc4, float4* __restrict__ out4,
       int S, int ML, int size, int tok, int nch) {
    int b    = blockIdx.y;
    int ch   = blockIdx.x;
    int tid  = threadIdx.x;
    int warp = tid >> 5;
    int lane = tid & 31;
    int gbid = blockIdx.y * gridDim.x + blockIdx.x;   // 0..511
    int t0   = ch * CHUNK;
    int t1   = min(t0 + CHUNK, size);
    unsigned expected = gridDim.x * gridDim.y;

    __shared__ float xs[BB][CSEG];   // phase 0 only
    __shared__ float qs[DK];
    __shared__ float es[CHUNK];      // exp values (live across phases)
    __shared__ float run[CHUNK];     // inclusive scalar prefix within chunk
    __shared__ float ssum[MAXCH];
    __shared__ float sbase[1];

    // ================= Phase 0: QKV projection partials ====================
    {
        int jt  = gbid & 3;          // 0..3
        int seg = gbid >> 2;         // 0..127
        int c0  = seg * CSEG;
        if (tid < BB * CSEG) {
            int pb = tid / CSEG, cc = tid % CSEG;
            xs[pb][cc] = x[(size_t)pb * S * CC + (size_t)(S - 1) * CC + c0 + cc];
        }
        __syncthreads();
        if (tid < JTW) {
            int j4 = jt * JTW + tid;
            float4 a0 = make_float4(0.f, 0.f, 0.f, 0.f);
            float4 a1 = a0, a2 = a0, a3 = a0;
#pragma unroll
            for (int cc = 0; cc < CSEG; cc++) {
                float4 w = __ldcs(&W4[(size_t)(c0 + cc) * TDK4 + j4]);
                float x0 = xs[0][cc], x1 = xs[1][cc], x2 = xs[2][cc], x3 = xs[3][cc];
                a0.x += x0 * w.x; a0.y += x0 * w.y; a0.z += x0 * w.z; a0.w += x0 * w.w;
                a1.x += x1 * w.x; a1.y += x1 * w.y; a1.z += x1 * w.z; a1.w += x1 * w.w;
                a2.x += x2 * w.x; a2.y += x2 * w.y; a2.z += x2 * w.z; a2.w += x2 * w.w;
                a3.x += x3 * w.x; a3.y += x3 * w.y; a3.z += x3 * w.z; a3.w += x3 * w.w;
            }
            g_qkv_part[(size_t)(seg * BB + 0) * TDK4 + j4] = a0;
            g_qkv_part[(size_t)(seg * BB + 1) * TDK4 + j4] = a1;
            g_qkv_part[(size_t)(seg * BB + 2) * TDK4 + j4] = a2;
            g_qkv_part[(size_t)(seg * BB + 3) * TDK4 + j4] = a3;
        }
    }
    grid_barrier(&g_bar[0], expected);

    // ================= Phase 0b: reduce partials + bias (warp/output) ======
    {
        int gw = gbid * 8 + warp;               // 0..4095; need 3072
        if (gw < BB * TDK4) {
            int rb = gw / TDK4, j4 = gw % TDK4;
            float4 s = make_float4(0.f, 0.f, 0.f, 0.f);
#pragma unroll
            for (int sg = lane; sg < NSEG; sg += 32) {
                float4 p = __ldcg(&g_qkv_part[(size_t)(sg * BB + rb) * TDK4 + j4]);
                s.x += p.x; s.y += p.y; s.z += p.z; s.w += p.w;
            }
#pragma unroll
            for (int o = 16; o; o >>= 1) {
                s.x += __shfl_xor_sync(0xFFFFFFFFu, s.x, o);
                s.y += __shfl_xor_sync(0xFFFFFFFFu, s.y, o);
                s.z += __shfl_xor_sync(0xFFFFFFFFu, s.z, o);
                s.w += __shfl_xor_sync(0xFFFFFFFFu, s.w, o);
            }
            if (lane == 0) {
                float4 bs = bias4[j4];
                s.x += bs.x; s.y += bs.y; s.z += bs.z; s.w += bs.w;
                ((float4*)g_qkv)[(size_t)rb * TDK4 + j4] = s;
            }
        }
    }
    grid_barrier(&g_bar[1], expected);

    // ================= Phase 1: logits + exp + chunk partials ==============
    for (int i = tid; i < DK; i += 256)
        qs[i] = __ldcg(&g_qkv[(size_t)b * TDK + i]);
    __syncthreads();

#pragma unroll
    for (int r = 0; r < 4; r++) {
        int t = t0 + warp * 4 + r;
        float acc = 0.f;
        if (t < size) {
            const float* krow = (t == tok) ? (g_qkv + (size_t)b * TDK + DK)
                                           : (kc + ((size_t)b * ML + t) * DK);
#pragma unroll
            for (int i = 0; i < 8; i++) {
                float4 kv = __ldcs((const float4*)(krow + i * 128 + lane * 4));
                float4 qv = *(const float4*)(qs + i * 128 + lane * 4);
                acc += kv.x * qv.x + kv.y * qv.y + kv.z * qv.z + kv.w * qv.w;
            }
#pragma unroll
            for (int o = 16; o; o >>= 1) acc += __shfl_xor_sync(0xFFFFFFFFu, acc, o);
        }
        if (lane == 0)
            es[warp * 4 + r] = (t < size) ? __expf(acc * 0.03125f) : 0.f;
    }
    __syncthreads();

    // intra-chunk scalar scan + chunk sum (warp 0)
    if (tid < 32) {
        float e = es[tid];
        float v = e;
#pragma unroll
        for (int o = 1; o < 32; o <<= 1) {
            float u = __shfl_up_sync(0xFFFFFFFFu, v, o);
            if (tid >= o) v += u;
        }
        run[tid] = v;
        float s = __shfl_sync(0xFFFFFFFFu, v, 31);
        if (tid == 0) g_se[(size_t)b * MAXCH + ch] = s;
    }
    __syncthreads();

    // vector partial over this chunk (V lands in this SM's L1 + L2)
    const float4* vb = vc4 + (size_t)b * ML * DK4;
    float4 vnew = __ldcg((const float4*)(g_qkv + (size_t)b * TDK + 2 * DK + 4 * tid));
    {
        float4 acc = make_float4(0.f, 0.f, 0.f, 0.f);
#pragma unroll 4
        for (int t = t0; t < t1; t++) {
            float4 v = (t == tok) ? vnew : __ldg(&vb[(size_t)t * DK4 + tid]);
            float e = es[t - t0];
            acc.x += e * v.x; acc.y += e * v.y; acc.z += e * v.z; acc.w += e * v.w;
        }
        g_P[((size_t)b * DK4 + tid) * MAXCH + ch] = acc;
    }

    grid_barrier(&g_bar[2], expected);

    // ================= Phase 2: warp-per-column exclusive prefix ============
    {
        int gw = gbid * 8 + warp;               // global warp id
        if (gw < BB * DK4) {
            float4* col = g_P + (size_t)gw * MAXCH;
            int base = lane * 4;
            float4 z = make_float4(0.f, 0.f, 0.f, 0.f);
            float4 v0 = (base + 0 < nch) ? __ldcg(&col[base + 0]) : z;
            float4 v1 = (base + 1 < nch) ? __ldcg(&col[base + 1]) : z;
            float4 v2 = (base + 2 < nch) ? __ldcg(&col[base + 2]) : z;
            float4 v3 = (base + 3 < nch) ? __ldcg(&col[base + 3]) : z;

            float4 tot = make_float4(v0.x + v1.x + v2.x + v3.x,
                                     v0.y + v1.y + v2.y + v3.y,
                                     v0.z + v1.z + v2.z + v3.z,
                                     v0.w + v1.w + v2.w + v3.w);
            float4 sc = tot;
#pragma unroll
            for (int o = 1; o < 32; o <<= 1) {
                float ux = __shfl_up_sync(0xFFFFFFFFu, sc.x, o);
                float uy = __shfl_up_sync(0xFFFFFFFFu, sc.y, o);
                float uz = __shfl_up_sync(0xFFFFFFFFu, sc.z, o);
                float uw = __shfl_up_sync(0xFFFFFFFFu, sc.w, o);
                if (lane >= o) { sc.x += ux; sc.y += uy; sc.z += uz; sc.w += uw; }
            }
            float4 r0 = make_float4(sc.x - tot.x, sc.y - tot.y,
                                    sc.z - tot.z, sc.w - tot.w);
            float4 r1 = make_float4(r0.x + v0.x, r0.y + v0.y, r0.z + v0.z, r0.w + v0.w);
            float4 r2 = make_float4(r1.x + v1.x, r1.y + v1.y, r1.z + v1.z, r1.w + v1.w);
            float4 r3 = make_float4(r2.x + v2.x, r2.y + v2.y, r2.z + v2.z, r2.w + v2.w);
            if (base + 0 < nch) col[base + 0] = r0;
            if (base + 1 < nch) col[base + 1] = r1;
            if (base + 2 < nch) col[base + 2] = r2;
            if (base + 3 < nch) col[base + 3] = r3;
        }
    }

    grid_barrier(&g_bar[3], expected);

    // ================= Phase 3: output (same chunk -> V is L1/L2 hot) ======
    for (int i = tid; i < nch; i += 256)
        ssum[i] = __ldcg(&g_se[(size_t)b * MAXCH + i]);
    __syncthreads();
    if (tid < 32) {
        float s = 0.f;
        for (int j = tid; j < ch; j += 32) s += ssum[j];
#pragma unroll
        for (int o = 16; o; o >>= 1) s += __shfl_xor_sync(0xFFFFFFFFu, s, o);
        if (tid == 0) sbase[0] = s;
    }
    float4 acc = __ldcg(&g_P[((size_t)b * DK4 + tid) * MAXCH + ch]);
    __syncthreads();
    float base_se = sbase[0];

#pragma unroll 4
    for (int t = t0; t < t1; t++) {
        float4 v = (t == tok) ? vnew : __ldg(&vb[(size_t)t * DK4 + tid]);
        float e = es[t - t0];
        acc.x += e * v.x; acc.y += e * v.y; acc.z += e * v.z; acc.w += e * v.w;
        float d = 1.0f / (base_se + run[t - t0]);
        float4 o = make_float4(acc.x * d, acc.y * d, acc.z * d, acc.w * d);
        __stcs(&out4[((size_t)b * size + t) * DK4 + tid], o);
    }

    // ================= Self-reset of barrier counters (graph-replay safe) ===
    // Each block increments ack only AFTER exiting all barrier spins; the last
    // incrementer resets everything for the next replay. No block reads the
    // barriers after its ack, so the reset cannot deadlock anyone.
    __syncthreads();
    if (tid == 0) {
        unsigned a = atomicAdd(&g_bar[4], 1u);
        if (a == expected - 1u) {
            g_bar[0] = 0u; g_bar[1] = 0u; g_bar[2] = 0u; g_bar[3] = 0u;
            __threadfence();
            g_bar[4] = 0u;
        }
    }
}

// ---------------- launch ----------------
extern "C" void kernel_launch(void* const* d_in, const int* in_sizes, int n_in,
                              void* d_out, int out_size) {
    const float* x    = (const float*)d_in[0];
    const float* W    = (const float*)d_in[1];
    const float* bias = (const float*)d_in[2];
    const float* kc   = (const float*)d_in[3];
    const float* vc   = (const float*)d_in[4];
    int S    = in_sizes[0] / (BB * CC);
    int ML   = in_sizes[3] / (BB * DK);
    int size = out_size / (BB * DK);
    int tok  = size - 1;
    int nch  = (size + CHUNK - 1) / CHUNK;

    k_mega<<<dim3(nch, BB), 256>>>(x, (const float4*)W, (const float4*)bias,
                                   kc, (const float4*)vc, (float4*)d_out,
                                   S, ML, size, tok, nch);
}

// round 12
// speedup vs baseline: 1.0588x; 1.0040x over previous
#include <cuda_runtime.h>
#include <math.h>
#include <float.h>

// Problem constants: B=4, C=1024, DK=1024, 3DK=3072, size = out_size/(B*DK)
#define BB 4
#define CC 1024
#define DK 1024
#define DK4 (DK / 4)          // 256 float4 per row
#define TDK 3072
#define TDK4 (TDK / 4)        // 768 float4 per W row
#define NSEG 128
#define CSEG (CC / NSEG)      // 8
#define JTW 192               // j4 per tile; 4 tiles * 192 = 768
#define CHUNK 32
#define MAXCH 128             // supports size up to 4096 (this problem: 4096)

// -------- scratch (device globals; zero-initialized at module load) --------
__device__ float4   g_qkv_part[NSEG * BB * TDK4];   // projection partials
__device__ float    g_qkv[BB * TDK];                // q | k_new | v_new
__device__ float    g_se[BB * MAXCH];               // per-chunk scalar e-sums
// TRANSPOSED: [b][c4][ch] so the prefix scan reads contiguous runs per column
__device__ float4   g_P[BB * DK4 * MAXCH];
__device__ unsigned g_bar[5];                       // 4 barriers + ack counter

// ---------------- software grid barrier (all blocks co-resident) ------------
__device__ __forceinline__ void grid_barrier(unsigned* bar, unsigned expected) {
    __syncthreads();
    if (threadIdx.x == 0) {
        __threadfence();                         // publish this block's writes
        atomicAdd(bar, 1u);
        volatile unsigned* vb = bar;
        while (*vb < expected) { }
    }
    __syncthreads();
}

// ---------------- MEGA: proj | reduce | logits+partials | prefix | output ---
// grid (nch, B) = 512 blocks, 256 thr. __launch_bounds__(256,4) keeps regs<=64
// so >=4 blocks/SM -> all 512 co-resident -> barriers safe.
__global__ void __launch_bounds__(256, 4)
k_mega(const float* __restrict__ x, const float4* __restrict__ W4,
       const float4* __restrict__ bias4, const float* __restrict__ kc,
       const float4* __restrict__ vc4, float4* __restrict__ out4,
       int S, int ML, int size, int tok, int nch) {
    int b    = blockIdx.y;
    int ch   = blockIdx.x;
    int tid  = threadIdx.x;
    int warp = tid >> 5;
    int lane = tid & 31;
    int gbid = blockIdx.y * gridDim.x + blockIdx.x;   // 0..511
    int t0   = ch * CHUNK;
    int t1   = min(t0 + CHUNK, size);
    unsigned expected = gridDim.x * gridDim.y;

    __shared__ float xs[BB][CSEG];   // phase 0 only
    __shared__ float qs[DK];
    __shared__ float es[CHUNK];      // exp values (live across phases)
    __shared__ float run[CHUNK];     // inclusive scalar prefix within chunk
    __shared__ float ssum[MAXCH];
    __shared__ float sbase[1];

    // ================= Phase 0: QKV projection partials ====================
    {
        int jt  = gbid & 3;          // 0..3
        int seg = gbid >> 2;         // 0..127
        int c0  = seg * CSEG;
        if (tid < BB * CSEG) {
            int pb = tid / CSEG, cc = tid % CSEG;
            xs[pb][cc] = x[(size_t)pb * S * CC + (size_t)(S - 1) * CC + c0 + cc];
        }
        __syncthreads();
        if (tid < JTW) {
            int j4 = jt * JTW + tid;
            float4 a0 = make_float4(0.f, 0.f, 0.f, 0.f);
            float4 a1 = a0, a2 = a0, a3 = a0;
#pragma unroll
            for (int cc = 0; cc < CSEG; cc++) {
                float4 w = __ldcs(&W4[(size_t)(c0 + cc) * TDK4 + j4]);
                float x0 = xs[0][cc], x1 = xs[1][cc], x2 = xs[2][cc], x3 = xs[3][cc];
                a0.x += x0 * w.x; a0.y += x0 * w.y; a0.z += x0 * w.z; a0.w += x0 * w.w;
                a1.x += x1 * w.x; a1.y += x1 * w.y; a1.z += x1 * w.z; a1.w += x1 * w.w;
                a2.x += x2 * w.x; a2.y += x2 * w.y; a2.z += x2 * w.z; a2.w += x2 * w.w;
                a3.x += x3 * w.x; a3.y += x3 * w.y; a3.z += x3 * w.z; a3.w += x3 * w.w;
            }
            g_qkv_part[(size_t)(seg * BB + 0) * TDK4 + j4] = a0;
            g_qkv_part[(size_t)(seg * BB + 1) * TDK4 + j4] = a1;
            g_qkv_part[(size_t)(seg * BB + 2) * TDK4 + j4] = a2;
            g_qkv_part[(size_t)(seg * BB + 3) * TDK4 + j4] = a3;
        }
    }
    grid_barrier(&g_bar[0], expected);

    // ================= Phase 0b: reduce partials + bias (warp/output) ======
    {
        int gw = gbid * 8 + warp;               // 0..4095; need 3072
        if (gw < BB * TDK4) {
            int rb = gw / TDK4, j4 = gw % TDK4;
            float4 s = make_float4(0.f, 0.f, 0.f, 0.f);
#pragma unroll
            for (int sg = lane; sg < NSEG; sg += 32) {
                float4 p = __ldcg(&g_qkv_part[(size_t)(sg * BB + rb) * TDK4 + j4]);
                s.x += p.x; s.y += p.y; s.z += p.z; s.w += p.w;
            }
#pragma unroll
            for (int o = 16; o; o >>= 1) {
                s.x += __shfl_xor_sync(0xFFFFFFFFu, s.x, o);
                s.y += __shfl_xor_sync(0xFFFFFFFFu, s.y, o);
                s.z += __shfl_xor_sync(0xFFFFFFFFu, s.z, o);
                s.w += __shfl_xor_sync(0xFFFFFFFFu, s.w, o);
            }
            if (lane == 0) {
                float4 bs = bias4[j4];
                s.x += bs.x; s.y += bs.y; s.z += bs.z; s.w += bs.w;
                ((float4*)g_qkv)[(size_t)rb * TDK4 + j4] = s;
            }
        }
    }
    grid_barrier(&g_bar[1], expected);

    // ================= Phase 1: logits (4 rows interleaved) + partials ======
    for (int i = tid; i < DK; i += 256)
        qs[i] = __ldcg(&g_qkv[(size_t)b * TDK + i]);
    __syncthreads();

    {
        int tw = t0 + warp * 4;
        // clamped row pointers (rows >= size read row size-1 harmlessly; e zeroed)
        const float* kr0; const float* kr1; const float* kr2; const float* kr3;
        {
            int ta = min(tw + 0, size - 1);
            int tb2 = min(tw + 1, size - 1);
            int tc = min(tw + 2, size - 1);
            int td = min(tw + 3, size - 1);
            kr0 = (ta == tok) ? (g_qkv + (size_t)b * TDK + DK) : (kc + ((size_t)b * ML + ta) * DK);
            kr1 = (tb2 == tok) ? (g_qkv + (size_t)b * TDK + DK) : (kc + ((size_t)b * ML + tb2) * DK);
            kr2 = (tc == tok) ? (g_qkv + (size_t)b * TDK + DK) : (kc + ((size_t)b * ML + tc) * DK);
            kr3 = (td == tok) ? (g_qkv + (size_t)b * TDK + DK) : (kc + ((size_t)b * ML + td) * DK);
        }
        float acc0 = 0.f, acc1 = 0.f, acc2 = 0.f, acc3 = 0.f;
#pragma unroll
        for (int i = 0; i < 8; i++) {
            int off = i * 128 + lane * 4;
            float4 qv = *(const float4*)(qs + off);
            float4 k0 = __ldcs((const float4*)(kr0 + off));
            float4 k1 = __ldcs((const float4*)(kr1 + off));
            float4 k2 = __ldcs((const float4*)(kr2 + off));
            float4 k3 = __ldcs((const float4*)(kr3 + off));
            acc0 += k0.x * qv.x + k0.y * qv.y + k0.z * qv.z + k0.w * qv.w;
            acc1 += k1.x * qv.x + k1.y * qv.y + k1.z * qv.z + k1.w * qv.w;
            acc2 += k2.x * qv.x + k2.y * qv.y + k2.z * qv.z + k2.w * qv.w;
            acc3 += k3.x * qv.x + k3.y * qv.y + k3.z * qv.z + k3.w * qv.w;
        }
#pragma unroll
        for (int o = 16; o; o >>= 1) {
            acc0 += __shfl_xor_sync(0xFFFFFFFFu, acc0, o);
            acc1 += __shfl_xor_sync(0xFFFFFFFFu, acc1, o);
            acc2 += __shfl_xor_sync(0xFFFFFFFFu, acc2, o);
            acc3 += __shfl_xor_sync(0xFFFFFFFFu, acc3, o);
        }
        if (lane == 0) {
            es[warp * 4 + 0] = (tw + 0 < size) ? __expf(acc0 * 0.03125f) : 0.f;
            es[warp * 4 + 1] = (tw + 1 < size) ? __expf(acc1 * 0.03125f) : 0.f;
            es[warp * 4 + 2] = (tw + 2 < size) ? __expf(acc2 * 0.03125f) : 0.f;
            es[warp * 4 + 3] = (tw + 3 < size) ? __expf(acc3 * 0.03125f) : 0.f;
        }
    }
    __syncthreads();

    // intra-chunk scalar scan + chunk sum (warp 0)
    if (tid < 32) {
        float e = es[tid];
        float v = e;
#pragma unroll
        for (int o = 1; o < 32; o <<= 1) {
            float u = __shfl_up_sync(0xFFFFFFFFu, v, o);
            if (tid >= o) v += u;
        }
        run[tid] = v;
        float s = __shfl_sync(0xFFFFFFFFu, v, 31);
        if (tid == 0) g_se[(size_t)b * MAXCH + ch] = s;
    }
    __syncthreads();

    // vector partial over this chunk (V lands in this SM's L1 + L2)
    const float4* vb = vc4 + (size_t)b * ML * DK4;
    float4 vnew = __ldcg((const float4*)(g_qkv + (size_t)b * TDK + 2 * DK + 4 * tid));
    {
        float4 accA = make_float4(0.f, 0.f, 0.f, 0.f);
        float4 accB = make_float4(0.f, 0.f, 0.f, 0.f);
#pragma unroll 8
        for (int t = t0; t < t1; t += 2) {
            float4 va = (t == tok) ? vnew : __ldg(&vb[(size_t)t * DK4 + tid]);
            float4 vbv = (t + 1 == tok) ? vnew : __ldg(&vb[(size_t)(t + 1) * DK4 + tid]);
            float ea = es[t - t0];
            float eb = es[t + 1 - t0];
            accA.x += ea * va.x; accA.y += ea * va.y; accA.z += ea * va.z; accA.w += ea * va.w;
            accB.x += eb * vbv.x; accB.y += eb * vbv.y; accB.z += eb * vbv.z; accB.w += eb * vbv.w;
        }
        float4 acc = make_float4(accA.x + accB.x, accA.y + accB.y,
                                 accA.z + accB.z, accA.w + accB.w);
        g_P[((size_t)b * DK4 + tid) * MAXCH + ch] = acc;
    }

    grid_barrier(&g_bar[2], expected);

    // ================= Phase 2: warp-per-column exclusive prefix ============
    {
        int gw = gbid * 8 + warp;               // global warp id
        if (gw < BB * DK4) {
            float4* col = g_P + (size_t)gw * MAXCH;
            int base = lane * 4;
            float4 z = make_float4(0.f, 0.f, 0.f, 0.f);
            float4 v0 = (base + 0 < nch) ? __ldcg(&col[base + 0]) : z;
            float4 v1 = (base + 1 < nch) ? __ldcg(&col[base + 1]) : z;
            float4 v2 = (base + 2 < nch) ? __ldcg(&col[base + 2]) : z;
            float4 v3 = (base + 3 < nch) ? __ldcg(&col[base + 3]) : z;

            float4 tot = make_float4(v0.x + v1.x + v2.x + v3.x,
                                     v0.y + v1.y + v2.y + v3.y,
                                     v0.z + v1.z + v2.z + v3.z,
                                     v0.w + v1.w + v2.w + v3.w);
            float4 sc = tot;
#pragma unroll
            for (int o = 1; o < 32; o <<= 1) {
                float ux = __shfl_up_sync(0xFFFFFFFFu, sc.x, o);
                float uy = __shfl_up_sync(0xFFFFFFFFu, sc.y, o);
                float uz = __shfl_up_sync(0xFFFFFFFFu, sc.z, o);
                float uw = __shfl_up_sync(0xFFFFFFFFu, sc.w, o);
                if (lane >= o) { sc.x += ux; sc.y += uy; sc.z += uz; sc.w += uw; }
            }
            float4 r0 = make_float4(sc.x - tot.x, sc.y - tot.y,
                                    sc.z - tot.z, sc.w - tot.w);
            float4 r1 = make_float4(r0.x + v0.x, r0.y + v0.y, r0.z + v0.z, r0.w + v0.w);
            float4 r2 = make_float4(r1.x + v1.x, r1.y + v1.y, r1.z + v1.z, r1.w + v1.w);
            float4 r3 = make_float4(r2.x + v2.x, r2.y + v2.y, r2.z + v2.z, r2.w + v2.w);
            if (base + 0 < nch) col[base + 0] = r0;
            if (base + 1 < nch) col[base + 1] = r1;
            if (base + 2 < nch) col[base + 2] = r2;
            if (base + 3 < nch) col[base + 3] = r3;
        }
    }

    grid_barrier(&g_bar[3], expected);

    // ================= Phase 3: output (same chunk -> V is L1/L2 hot) ======
    for (int i = tid; i < nch; i += 256)
        ssum[i] = __ldcg(&g_se[(size_t)b * MAXCH + i]);
    __syncthreads();
    if (tid < 32) {
        float s = 0.f;
        for (int j = tid; j < ch; j += 32) s += ssum[j];
#pragma unroll
        for (int o = 16; o; o >>= 1) s += __shfl_xor_sync(0xFFFFFFFFu, s, o);
        if (tid == 0) sbase[0] = s;
    }
    float4 acc = __ldcg(&g_P[((size_t)b * DK4 + tid) * MAXCH + ch]);
    __syncthreads();
    float base_se = sbase[0];

#pragma unroll 8
    for (int t = t0; t < t1; t++) {
        float4 v = (t == tok) ? vnew : __ldg(&vb[(size_t)t * DK4 + tid]);
        float e = es[t - t0];
        acc.x += e * v.x; acc.y += e * v.y; acc.z += e * v.z; acc.w += e * v.w;
        float d = 1.0f / (base_se + run[t - t0]);
        float4 o = make_float4(acc.x * d, acc.y * d, acc.z * d, acc.w * d);
        __stcs(&out4[((size_t)b * size + t) * DK4 + tid], o);
    }

    // ================= Self-reset of barrier counters (graph-replay safe) ===
    __syncthreads();
    if (tid == 0) {
        unsigned a = atomicAdd(&g_bar[4], 1u);
        if (a == expected - 1u) {
            g_bar[0] = 0u; g_bar[1] = 0u; g_bar[2] = 0u; g_bar[3] = 0u;
            __threadfence();
            g_bar[4] = 0u;
        }
    }
}

// ---------------- launch ----------------
extern "C" void kernel_launch(void* const* d_in, const int* in_sizes, int n_in,
                              void* d_out, int out_size) {
    const float* x    = (const float*)d_in[0];
    const float* W    = (const float*)d_in[1];
    const float* bias = (const float*)d_in[2];
    const float* kc   = (const float*)d_in[3];
    const float* vc   = (const float*)d_in[4];
    int S    = in_sizes[0] / (BB * CC);
    int ML   = in_sizes[3] / (BB * DK);
    int size = out_size / (BB * DK);
    int tok  = size - 1;
    int nch  = (size + CHUNK - 1) / CHUNK;

    k_mega<<<dim3(nch, BB), 256>>>(x, (const float4*)W, (const float4*)bias,
                                   kc, (const float4*)vc, (float4*)d_out,
                                   S, ML, size, tok, nch);
}